// round 1
// baseline (speedup 1.0000x reference)
#include <cuda_runtime.h>

#define BB 16
#define NN 1024
#define DD 128
#define BN (BB*NN)

// ---------------- scratch (static device globals; no allocation) ----------------
__device__ float g_WwT[DD*DD];
__device__ float g_h  [BN*DD];
__device__ float g_hA [BN*DD];
__device__ float g_scores[(size_t)BB*NN*NN];
__device__ float g_rz [BB*NN];
__device__ float g_hp [BN*DD];

// ---------------- K0: transpose Ww ----------------
__global__ void k_transpose(const float* __restrict__ Ww) {
    int i = blockIdx.x * 256 + threadIdx.x;
    int d = i >> 7, f = i & 127;
    g_WwT[f * DD + d] = Ww[d * DD + f];
}

// ---------------- K1: fused h = x@Ww^T + Wb ; hA = h@A ----------------
__global__ __launch_bounds__(256) void k_h_hA(const float* __restrict__ x,
                                              const float* __restrict__ A,
                                              const float* __restrict__ Wb) {
    __shared__ float sX[64 * 128];
    int t = threadIdx.x;
    int tx = t & 31, ty = t >> 5;
    int row0 = blockIdx.x * 64;

    #pragma unroll
    for (int i = 0; i < 32; i++) {
        int idx = i * 256 + t;
        sX[idx] = x[(size_t)row0 * DD + idx];
    }
    __syncthreads();

    float acc[8][4];
    float4 wb4 = *(const float4*)&Wb[tx * 4];
    #pragma unroll
    for (int i = 0; i < 8; i++) { acc[i][0]=wb4.x; acc[i][1]=wb4.y; acc[i][2]=wb4.z; acc[i][3]=wb4.w; }
    for (int f = 0; f < 128; f++) {
        float4 w = *(const float4*)&g_WwT[f * DD + tx * 4];
        #pragma unroll
        for (int i = 0; i < 8; i++) {
            float xv = sX[(ty * 8 + i) * 128 + f];
            acc[i][0] += xv * w.x; acc[i][1] += xv * w.y;
            acc[i][2] += xv * w.z; acc[i][3] += xv * w.w;
        }
    }
    __syncthreads();
    #pragma unroll
    for (int i = 0; i < 8; i++) {
        int r = ty * 8 + i;
        float4 v; v.x = acc[i][0]; v.y = acc[i][1]; v.z = acc[i][2]; v.w = acc[i][3];
        *(float4*)&g_h[(size_t)(row0 + r) * DD + tx * 4] = v;
        *(float4*)&sX[r * 128 + tx * 4] = v;
    }
    __syncthreads();

    float acc2[8][4];
    #pragma unroll
    for (int i = 0; i < 8; i++) { acc2[i][0]=0.f; acc2[i][1]=0.f; acc2[i][2]=0.f; acc2[i][3]=0.f; }
    for (int f = 0; f < 128; f++) {
        float4 a4 = *(const float4*)&A[f * DD + tx * 4];
        #pragma unroll
        for (int i = 0; i < 8; i++) {
            float hv = sX[(ty * 8 + i) * 128 + f];
            acc2[i][0] += hv * a4.x; acc2[i][1] += hv * a4.y;
            acc2[i][2] += hv * a4.z; acc2[i][3] += hv * a4.w;
        }
    }
    #pragma unroll
    for (int i = 0; i < 8; i++) {
        float4 v; v.x = acc2[i][0]; v.y = acc2[i][1]; v.z = acc2[i][2]; v.w = acc2[i][3];
        *(float4*)&g_hA[(size_t)(row0 + ty * 8 + i) * DD + tx * 4] = v;
    }
}

// ---------------- K3: scores (upper-triangular tiles + mirrored write) ----------------
#define LDT 33
__global__ __launch_bounds__(256) void k_scores(const float* __restrict__ adj) {
    extern __shared__ float sm[];
    float* sHAj = sm;
    float* sHj  = sm + 1 * 128 * LDT;
    float* sHk  = sm + 2 * 128 * LDT;
    float* sHAk = sm + 3 * 128 * LDT;

    int u = blockIdx.x, b = blockIdx.y;
    int tj = 0, rem = u;
    while (rem >= 8 - tj) { rem -= 8 - tj; tj++; }
    int tk = tj + rem;
    int j0 = tj * 128, k0 = tk * 128;

    int t = threadIdx.x, tx = t & 15, ty = t >> 4;
    const float* Hb  = g_h  + (size_t)b * NN * DD;
    const float* HAb = g_hA + (size_t)b * NN * DD;

    float acc[8][8];
    #pragma unroll
    for (int i = 0; i < 8; i++)
        #pragma unroll
        for (int j = 0; j < 8; j++) acc[i][j] = 0.f;

    for (int ch = 0; ch < 4; ch++) {
        int c = t & 31, r0 = t >> 5;
        #pragma unroll
        for (int i = 0; i < 16; i++) {
            int r = r0 + 8 * i;
            sHAj[r * LDT + c] = HAb[(size_t)(j0 + r) * DD + ch * 32 + c];
            sHj [r * LDT + c] = Hb [(size_t)(j0 + r) * DD + ch * 32 + c];
            sHk [r * LDT + c] = Hb [(size_t)(k0 + r) * DD + ch * 32 + c];
            sHAk[r * LDT + c] = HAb[(size_t)(k0 + r) * DD + ch * 32 + c];
        }
        __syncthreads();
        for (int kk = 0; kk < 32; kk++) {
            float a1[8], a2[8], b1[8], b2[8];
            #pragma unroll
            for (int i = 0; i < 8; i++) {
                a1[i] = sHAj[(ty * 8 + i) * LDT + kk];
                a2[i] = sHj [(ty * 8 + i) * LDT + kk];
                b1[i] = sHk [(tx * 8 + i) * LDT + kk];
                b2[i] = sHAk[(tx * 8 + i) * LDT + kk];
            }
            #pragma unroll
            for (int i = 0; i < 8; i++)
                #pragma unroll
                for (int j = 0; j < 8; j++)
                    acc[i][j] += a1[i] * b1[j] + a2[i] * b2[j];
        }
        __syncthreads();
    }

    const float* adjb = adj + (size_t)b * NN * NN;
    float* scb = g_scores + (size_t)b * NN * NN;

    #pragma unroll
    for (int i = 0; i < 8; i++) {
        int j = j0 + ty * 8 + i;
        #pragma unroll
        for (int jj = 0; jj < 8; jj += 4) {
            int k = k0 + tx * 8 + jj;
            float4 am = *(const float4*)&adjb[(size_t)j * NN + k];
            float4 v;
            v.x = am.x > 0.f ? acc[i][jj + 0] : 0.f;
            v.y = am.y > 0.f ? acc[i][jj + 1] : 0.f;
            v.z = am.z > 0.f ? acc[i][jj + 2] : 0.f;
            v.w = am.w > 0.f ? acc[i][jj + 3] : 0.f;
            *(float4*)&scb[(size_t)j * NN + k] = v;
        }
    }

    if (tj != tk) {
        float* sT = sm;  // 128*129 = 16512 floats fits in the 16896-float buffer
        #pragma unroll
        for (int i = 0; i < 8; i++)
            #pragma unroll
            for (int jj = 0; jj < 8; jj++)
                sT[(tx * 8 + jj) * 129 + (ty * 8 + i)] = acc[i][jj];
        __syncthreads();
        int c = t & 127, r0b = t >> 7;
        #pragma unroll 4
        for (int p = 0; p < 64; p++) {
            int r = r0b + 2 * p;
            int k = k0 + r, j = j0 + c;
            float am = adjb[(size_t)k * NN + j];
            scb[(size_t)k * NN + j] = am > 0.f ? sT[r * 129 + c] : 0.f;
        }
    }
}

// ---------------- K4: per-column 1/sum(exp) ----------------
__global__ __launch_bounds__(256) void k_colsum() {
    __shared__ float red[256];
    int b = blockIdx.y, k0 = blockIdx.x * 128;
    int t = threadIdx.x, c = t & 127, j0 = t >> 7;
    const float* scb = g_scores + (size_t)b * NN * NN + k0;
    float z = 0.f;
    #pragma unroll 4
    for (int j = j0; j < NN; j += 2)
        z += __expf(scb[(size_t)j * NN + c]);
    red[t] = z;
    __syncthreads();
    if (t < 128) g_rz[b * NN + k0 + c] = 1.0f / (red[t] + red[t + 128]);
}

// ---------------- K5: h_prime ----------------
__global__ __launch_bounds__(256) void k_hprime(const float* __restrict__ adj) {
    __shared__ float sA[64 * 33];
    __shared__ float sH[32 * 128];
    int b = blockIdx.y, i0 = blockIdx.x * 64;
    int t = threadIdx.x, tx = t & 31, ty = t >> 5;
    const float* scb  = g_scores + (size_t)b * NN * NN;
    const float* adjb = adj      + (size_t)b * NN * NN;
    const float* Hb   = g_h      + (size_t)b * NN * DD;
    const float* rzb  = g_rz     + b * NN;

    float acc[8][4];
    #pragma unroll
    for (int i = 0; i < 8; i++) { acc[i][0]=0.f; acc[i][1]=0.f; acc[i][2]=0.f; acc[i][3]=0.f; }

    for (int ch = 0; ch < 32; ch++) {
        int jbase = ch * 32;
        {
            int c = t & 31, r0 = t >> 5;
            #pragma unroll
            for (int p = 0; p < 8; p++) {
                int r = r0 + 8 * p;
                int j = jbase + c;
                float s  = scb [(size_t)(i0 + r) * NN + j];
                float am = adjb[(size_t)(i0 + r) * NN + j];
                sA[r * 33 + c] = am * __expf(s) * rzb[j];
            }
        }
        {
            int c2 = t & 127, r0b = t >> 7;
            #pragma unroll
            for (int p = 0; p < 16; p++) {
                int r = r0b + 2 * p;
                sH[r * 128 + c2] = Hb[(size_t)(jbase + r) * DD + c2];
            }
        }
        __syncthreads();
        for (int kk = 0; kk < 32; kk++) {
            float4 hv = *(const float4*)&sH[kk * 128 + tx * 4];
            #pragma unroll
            for (int i = 0; i < 8; i++) {
                float a = sA[(ty * 8 + i) * 33 + kk];
                acc[i][0] += a * hv.x; acc[i][1] += a * hv.y;
                acc[i][2] += a * hv.z; acc[i][3] += a * hv.w;
            }
        }
        __syncthreads();
    }
    float* hpb = g_hp + (size_t)b * NN * DD;
    #pragma unroll
    for (int i = 0; i < 8; i++) {
        float4 v;
        v.x = fmaxf(acc[i][0], 0.f); v.y = fmaxf(acc[i][1], 0.f);
        v.z = fmaxf(acc[i][2], 0.f); v.w = fmaxf(acc[i][3], 0.f);
        *(float4*)&hpb[(size_t)(i0 + ty * 8 + i) * DD + tx * 4] = v;
    }
}

// ---------------- K6: gates + output ----------------
__global__ __launch_bounds__(256) void k_out(const float* __restrict__ x,
        const float* __restrict__ wi_u, const float* __restrict__ wi_x,
        const float* __restrict__ wf_u, const float* __restrict__ wf_x,
        const float* __restrict__ wo_u, const float* __restrict__ wo_x,
        float* __restrict__ out) {
    int node = blockIdx.x * 8 + (threadIdx.x >> 5);
    int lane = threadIdx.x & 31;
    size_t base = (size_t)node * DD;
    float hp4[4], x4[4];
    float si = 0.f, sf = 0.f, so = 0.f;
    #pragma unroll
    for (int i = 0; i < 4; i++) {
        int d = lane + 32 * i;
        hp4[i] = g_hp[base + d];
        x4[i]  = x[base + d];
        si += hp4[i] * wi_u[d] + x4[i] * wi_x[d];
        sf += hp4[i] * wf_u[d] + x4[i] * wf_x[d];
        so += hp4[i] * wo_u[d] + x4[i] * wo_x[d];
    }
    #pragma unroll
    for (int off = 16; off; off >>= 1) {
        si += __shfl_xor_sync(0xffffffffu, si, off);
        sf += __shfl_xor_sync(0xffffffffu, sf, off);
        so += __shfl_xor_sync(0xffffffffu, so, off);
    }
    float ic = 1.f / (1.f + __expf(-si));
    float fc = 1.f / (1.f + __expf(-sf));
    float oc = 1.f / (1.f + __expf(-so));
    #pragma unroll
    for (int i = 0; i < 4; i++) {
        int d = lane + 32 * i;
        out[base + d] = oc * tanhf(ic * hp4[i] + fc * x4[i]);
    }
}

// ---------------- launch ----------------
extern "C" void kernel_launch(void* const* d_in, const int* in_sizes, int n_in,
                              void* d_out, int out_size) {
    const float* x    = (const float*)d_in[0];
    const float* adj  = (const float*)d_in[1];
    const float* Ww   = (const float*)d_in[2];
    const float* Wb   = (const float*)d_in[3];
    const float* A    = (const float*)d_in[4];
    const float* wi_u = (const float*)d_in[5];
    const float* wi_x = (const float*)d_in[6];
    const float* wf_u = (const float*)d_in[7];
    const float* wf_x = (const float*)d_in[8];
    const float* wo_u = (const float*)d_in[9];
    const float* wo_x = (const float*)d_in[10];
    float* out = (float*)d_out;

    cudaFuncSetAttribute(k_scores, cudaFuncAttributeMaxDynamicSharedMemorySize, 4 * 128 * LDT * 4);

    k_transpose<<<64, 256>>>(Ww);
    k_h_hA<<<BN / 64, 256>>>(x, A, Wb);
    k_scores<<<dim3(36, BB), 256, 4 * 128 * LDT * 4>>>(adj);
    k_colsum<<<dim3(NN / 128, BB), 256>>>();
    k_hprime<<<dim3(NN / 64, BB), 256>>>(adj);
    k_out<<<BN / 8, 256>>>(x, wi_u, wi_x, wf_u, wf_x, wo_u, wo_x, out);
}

// round 2
// speedup vs baseline: 1.0803x; 1.0803x over previous
#include <cuda_runtime.h>

#define BB 16
#define NN 1024
#define DD 128
#define BN (BB*NN)

// ---------------- scratch (static device globals; no allocation) ----------------
__device__ float g_WwT[DD*DD];
__device__ float g_h  [BN*DD];
__device__ float g_hA [BN*DD];
__device__ float g_scores[(size_t)BB*NN*NN];  // holds exp'd masked numerators
__device__ float g_z  [BB*NN];                // softmax denominators (atomic acc)
__device__ float g_rz [BB*NN];                // reciprocals
__device__ float g_hp [BN*DD];

// ---------------- K0: transpose Ww + zero g_z ----------------
__global__ void k_transpose(const float* __restrict__ Ww) {
    int i = blockIdx.x * 256 + threadIdx.x;   // 16384 threads == DD*DD == BB*NN
    int d = i >> 7, f = i & 127;
    g_WwT[f * DD + d] = Ww[d * DD + f];
    g_z[i] = 0.f;
}

// ---------------- K1: fused h = x@Ww^T + Wb ; hA = h@A ----------------
__global__ __launch_bounds__(256) void k_h_hA(const float* __restrict__ x,
                                              const float* __restrict__ A,
                                              const float* __restrict__ Wb) {
    __shared__ float sX[64 * 128];
    int t = threadIdx.x;
    int tx = t & 31, ty = t >> 5;
    int row0 = blockIdx.x * 64;

    #pragma unroll
    for (int i = 0; i < 32; i++) {
        int idx = i * 256 + t;
        sX[idx] = x[(size_t)row0 * DD + idx];
    }
    __syncthreads();

    float acc[8][4];
    float4 wb4 = *(const float4*)&Wb[tx * 4];
    #pragma unroll
    for (int i = 0; i < 8; i++) { acc[i][0]=wb4.x; acc[i][1]=wb4.y; acc[i][2]=wb4.z; acc[i][3]=wb4.w; }
    for (int f = 0; f < 128; f++) {
        float4 w = *(const float4*)&g_WwT[f * DD + tx * 4];
        #pragma unroll
        for (int i = 0; i < 8; i++) {
            float xv = sX[(ty * 8 + i) * 128 + f];
            acc[i][0] += xv * w.x; acc[i][1] += xv * w.y;
            acc[i][2] += xv * w.z; acc[i][3] += xv * w.w;
        }
    }
    __syncthreads();
    #pragma unroll
    for (int i = 0; i < 8; i++) {
        int r = ty * 8 + i;
        float4 v; v.x = acc[i][0]; v.y = acc[i][1]; v.z = acc[i][2]; v.w = acc[i][3];
        *(float4*)&g_h[(size_t)(row0 + r) * DD + tx * 4] = v;
        *(float4*)&sX[r * 128 + tx * 4] = v;
    }
    __syncthreads();

    float acc2[8][4];
    #pragma unroll
    for (int i = 0; i < 8; i++) { acc2[i][0]=0.f; acc2[i][1]=0.f; acc2[i][2]=0.f; acc2[i][3]=0.f; }
    for (int f = 0; f < 128; f++) {
        float4 a4 = *(const float4*)&A[f * DD + tx * 4];
        #pragma unroll
        for (int i = 0; i < 8; i++) {
            float hv = sX[(ty * 8 + i) * 128 + f];
            acc2[i][0] += hv * a4.x; acc2[i][1] += hv * a4.y;
            acc2[i][2] += hv * a4.z; acc2[i][3] += hv * a4.w;
        }
    }
    #pragma unroll
    for (int i = 0; i < 8; i++) {
        float4 v; v.x = acc2[i][0]; v.y = acc2[i][1]; v.z = acc2[i][2]; v.w = acc2[i][3];
        *(float4*)&g_hA[(size_t)(row0 + ty * 8 + i) * DD + tx * 4] = v;
    }
}

// ---------------- K3: scores -> exp'd numerators + fused column-sum atomics ----------------
// Upper-triangular 128x128 tiles; mirror through smem transpose.
// Writes n = adj>0 ? exp(e_sym) : 0 to g_scores.
// Accumulates z[k] += (adj>0 ? exp(e) : 1) via atomicAdd (masked entries
// contribute exp(0)=1 to the softmax denominator).
#define LDT 33
__global__ __launch_bounds__(256) void k_scores(const float* __restrict__ adj) {
    extern __shared__ float sm[];
    float* sHAj = sm;
    float* sHj  = sm + 1 * 128 * LDT;
    float* sHk  = sm + 2 * 128 * LDT;
    float* sHAk = sm + 3 * 128 * LDT;

    int u = blockIdx.x, b = blockIdx.y;
    int tj = 0, rem = u;
    while (rem >= 8 - tj) { rem -= 8 - tj; tj++; }
    int tk = tj + rem;
    int j0 = tj * 128, k0 = tk * 128;

    int t = threadIdx.x, tx = t & 15, ty = t >> 4;
    const float* Hb  = g_h  + (size_t)b * NN * DD;
    const float* HAb = g_hA + (size_t)b * NN * DD;

    float acc[8][8];
    #pragma unroll
    for (int i = 0; i < 8; i++)
        #pragma unroll
        for (int j = 0; j < 8; j++) acc[i][j] = 0.f;

    for (int ch = 0; ch < 4; ch++) {
        int c = t & 31, r0 = t >> 5;
        #pragma unroll
        for (int i = 0; i < 16; i++) {
            int r = r0 + 8 * i;
            sHAj[r * LDT + c] = HAb[(size_t)(j0 + r) * DD + ch * 32 + c];
            sHj [r * LDT + c] = Hb [(size_t)(j0 + r) * DD + ch * 32 + c];
            sHk [r * LDT + c] = Hb [(size_t)(k0 + r) * DD + ch * 32 + c];
            sHAk[r * LDT + c] = HAb[(size_t)(k0 + r) * DD + ch * 32 + c];
        }
        __syncthreads();
        for (int kk = 0; kk < 32; kk++) {
            float a1[8], a2[8], b1[8], b2[8];
            #pragma unroll
            for (int i = 0; i < 8; i++) {
                a1[i] = sHAj[(ty * 8 + i) * LDT + kk];
                a2[i] = sHj [(ty * 8 + i) * LDT + kk];
                b1[i] = sHk [(tx * 8 + i) * LDT + kk];
                b2[i] = sHAk[(tx * 8 + i) * LDT + kk];
            }
            #pragma unroll
            for (int i = 0; i < 8; i++)
                #pragma unroll
                for (int j = 0; j < 8; j++)
                    acc[i][j] += a1[i] * b1[j] + a2[i] * b2[j];
        }
        __syncthreads();
    }

    const float* adjb = adj + (size_t)b * NN * NN;
    float* scb = g_scores + (size_t)b * NN * NN;

    // ---- direct tile: exp + mask + write + per-thread column partials ----
    float colp[8];
    #pragma unroll
    for (int jj = 0; jj < 8; jj++) colp[jj] = 0.f;

    #pragma unroll
    for (int i = 0; i < 8; i++) {
        int j = j0 + ty * 8 + i;
        #pragma unroll
        for (int jj = 0; jj < 8; jj += 4) {
            int k = k0 + tx * 8 + jj;
            float4 am = *(const float4*)&adjb[(size_t)j * NN + k];
            float4 v;
            v.x = am.x > 0.f ? __expf(acc[i][jj + 0]) : 0.f;
            v.y = am.y > 0.f ? __expf(acc[i][jj + 1]) : 0.f;
            v.z = am.z > 0.f ? __expf(acc[i][jj + 2]) : 0.f;
            v.w = am.w > 0.f ? __expf(acc[i][jj + 3]) : 0.f;
            colp[jj + 0] += am.x > 0.f ? v.x : 1.f;
            colp[jj + 1] += am.y > 0.f ? v.y : 1.f;
            colp[jj + 2] += am.z > 0.f ? v.z : 1.f;
            colp[jj + 3] += am.w > 0.f ? v.w : 1.f;
            *(float4*)&scb[(size_t)j * NN + k] = v;
        }
    }

    // reduce column partials across the 16 ty-groups, one atomic per column
    float* sC = sm;  // 16 x 128 floats (sm free: compute phase ended with sync)
    #pragma unroll
    for (int jj = 0; jj < 8; jj++)
        sC[ty * 128 + tx * 8 + jj] = colp[jj];
    __syncthreads();
    if (t < 128) {
        float z = 0.f;
        #pragma unroll
        for (int q = 0; q < 16; q++) z += sC[q * 128 + t];
        atomicAdd(&g_z[b * NN + k0 + t], z);
    }

    // ---- mirrored tile (off-diagonal): transpose via smem, exp + mask + colsum ----
    if (tj != tk) {
        __syncthreads();  // sC reads done before reusing sm as sT
        float* sT = sm;   // 128*129 floats fits the 16896-float buffer
        #pragma unroll
        for (int i = 0; i < 8; i++)
            #pragma unroll
            for (int jj = 0; jj < 8; jj++)
                sT[(tx * 8 + jj) * 129 + (ty * 8 + i)] = acc[i][jj];
        __syncthreads();
        int c = t & 127, r0b = t >> 7;
        float zM = 0.f;
        #pragma unroll 4
        for (int p = 0; p < 64; p++) {
            int r = r0b + 2 * p;
            int k = k0 + r, j = j0 + c;
            float am = adjb[(size_t)k * NN + j];
            float ev = am > 0.f ? __expf(sT[r * 129 + c]) : 0.f;
            zM += am > 0.f ? ev : 1.f;
            scb[(size_t)k * NN + j] = ev;
        }
        atomicAdd(&g_z[b * NN + j0 + c], zM);
    }
}

// ---------------- K4: invert denominators ----------------
__global__ void k_invz() {
    int i = blockIdx.x * 256 + threadIdx.x;
    g_rz[i] = 1.0f / g_z[i];
}

// ---------------- K5: h_prime = relu( (n * rz_col) @ h ) ----------------
__global__ __launch_bounds__(256) void k_hprime() {
    __shared__ float sA[64 * 33];
    __shared__ float sH[32 * 128];
    int b = blockIdx.y, i0 = blockIdx.x * 64;
    int t = threadIdx.x, tx = t & 31, ty = t >> 5;
    const float* scb = g_scores + (size_t)b * NN * NN;
    const float* Hb  = g_h      + (size_t)b * NN * DD;
    const float* rzb = g_rz     + b * NN;

    float acc[8][4];
    #pragma unroll
    for (int i = 0; i < 8; i++) { acc[i][0]=0.f; acc[i][1]=0.f; acc[i][2]=0.f; acc[i][3]=0.f; }

    for (int ch = 0; ch < 32; ch++) {
        int jbase = ch * 32;
        {   // attention tile 64x32: numerator * reciprocal denominator (no exp, no adj)
            int c = t & 31, r0 = t >> 5;
            float rz = rzb[jbase + c];
            #pragma unroll
            for (int p = 0; p < 8; p++) {
                int r = r0 + 8 * p;
                sA[r * 33 + c] = scb[(size_t)(i0 + r) * NN + jbase + c] * rz;
            }
        }
        {   // h tile 32x128
            int c2 = t & 127, r0b = t >> 7;
            #pragma unroll
            for (int p = 0; p < 16; p++) {
                int r = r0b + 2 * p;
                sH[r * 128 + c2] = Hb[(size_t)(jbase + r) * DD + c2];
            }
        }
        __syncthreads();
        for (int kk = 0; kk < 32; kk++) {
            float4 hv = *(const float4*)&sH[kk * 128 + tx * 4];
            #pragma unroll
            for (int i = 0; i < 8; i++) {
                float a = sA[(ty * 8 + i) * 33 + kk];
                acc[i][0] += a * hv.x; acc[i][1] += a * hv.y;
                acc[i][2] += a * hv.z; acc[i][3] += a * hv.w;
            }
        }
        __syncthreads();
    }
    float* hpb = g_hp + (size_t)b * NN * DD;
    #pragma unroll
    for (int i = 0; i < 8; i++) {
        float4 v;
        v.x = fmaxf(acc[i][0], 0.f); v.y = fmaxf(acc[i][1], 0.f);
        v.z = fmaxf(acc[i][2], 0.f); v.w = fmaxf(acc[i][3], 0.f);
        *(float4*)&hpb[(size_t)(i0 + ty * 8 + i) * DD + tx * 4] = v;
    }
}

// ---------------- K6: gates + output ----------------
__global__ __launch_bounds__(256) void k_out(const float* __restrict__ x,
        const float* __restrict__ wi_u, const float* __restrict__ wi_x,
        const float* __restrict__ wf_u, const float* __restrict__ wf_x,
        const float* __restrict__ wo_u, const float* __restrict__ wo_x,
        float* __restrict__ out) {
    int node = blockIdx.x * 8 + (threadIdx.x >> 5);
    int lane = threadIdx.x & 31;
    size_t base = (size_t)node * DD;
    float hp4[4], x4[4];
    float si = 0.f, sf = 0.f, so = 0.f;
    #pragma unroll
    for (int i = 0; i < 4; i++) {
        int d = lane + 32 * i;
        hp4[i] = g_hp[base + d];
        x4[i]  = x[base + d];
        si += hp4[i] * wi_u[d] + x4[i] * wi_x[d];
        sf += hp4[i] * wf_u[d] + x4[i] * wf_x[d];
        so += hp4[i] * wo_u[d] + x4[i] * wo_x[d];
    }
    #pragma unroll
    for (int off = 16; off; off >>= 1) {
        si += __shfl_xor_sync(0xffffffffu, si, off);
        sf += __shfl_xor_sync(0xffffffffu, sf, off);
        so += __shfl_xor_sync(0xffffffffu, so, off);
    }
    float ic = 1.f / (1.f + __expf(-si));
    float fc = 1.f / (1.f + __expf(-sf));
    float oc = 1.f / (1.f + __expf(-so));
    #pragma unroll
    for (int i = 0; i < 4; i++) {
        int d = lane + 32 * i;
        out[base + d] = oc * tanhf(ic * hp4[i] + fc * x4[i]);
    }
}

// ---------------- launch ----------------
extern "C" void kernel_launch(void* const* d_in, const int* in_sizes, int n_in,
                              void* d_out, int out_size) {
    const float* x    = (const float*)d_in[0];
    const float* adj  = (const float*)d_in[1];
    const float* Ww   = (const float*)d_in[2];
    const float* Wb   = (const float*)d_in[3];
    const float* A    = (const float*)d_in[4];
    const float* wi_u = (const float*)d_in[5];
    const float* wi_x = (const float*)d_in[6];
    const float* wf_u = (const float*)d_in[7];
    const float* wf_x = (const float*)d_in[8];
    const float* wo_u = (const float*)d_in[9];
    const float* wo_x = (const float*)d_in[10];
    float* out = (float*)d_out;

    cudaFuncSetAttribute(k_scores, cudaFuncAttributeMaxDynamicSharedMemorySize, 4 * 128 * LDT * 4);

    k_transpose<<<64, 256>>>(Ww);
    k_h_hA<<<BN / 64, 256>>>(x, A, Wb);
    k_scores<<<dim3(36, BB), 256, 4 * 128 * LDT * 4>>>(adj);
    k_invz<<<64, 256>>>();
    k_hprime<<<dim3(NN / 64, BB), 256>>>();
    k_out<<<BN / 8, 256>>>(x, wi_u, wi_x, wf_u, wf_x, wo_u, wo_x, out);
}

// round 3
// speedup vs baseline: 1.3222x; 1.2240x over previous
#include <cuda_runtime.h>

#define BB 16
#define NN 1024
#define DD 128
#define BN (BB*NN)

// ---------------- scratch (static device globals; no allocation) ----------------
__device__ float g_WwT[DD*DD];
__device__ float g_M  [DD*DD];               // A + A^T
__device__ float g_h  [BN*DD];
__device__ float g_g  [BN*DD];               // g = h @ (A+A^T)
__device__ float g_scores[(size_t)BB*NN*NN]; // exp'd masked numerators
__device__ float g_z  [BB*NN];
__device__ float g_rz [BB*NN];
__device__ float g_hp [BN*DD];

// ---------------- K0: transpose Ww, form M = A+A^T, zero g_z ----------------
__global__ void k_prep(const float* __restrict__ Ww, const float* __restrict__ A) {
    int i = blockIdx.x * 256 + threadIdx.x;   // 16384 == DD*DD == BB*NN
    int d = i >> 7, f = i & 127;
    g_WwT[f * DD + d] = Ww[d * DD + f];
    g_M[d * DD + f] = A[d * DD + f] + A[f * DD + d];
    g_z[i] = 0.f;
}

// ---------------- K1: fused h = x@Ww^T + Wb ; g = h@M ----------------
__global__ __launch_bounds__(256) void k_h_g(const float* __restrict__ x,
                                             const float* __restrict__ Wb) {
    __shared__ float sX[64 * 128];
    int t = threadIdx.x;
    int tx = t & 31, ty = t >> 5;
    int row0 = blockIdx.x * 64;

    #pragma unroll
    for (int i = 0; i < 32; i++) {
        int idx = i * 256 + t;
        sX[idx] = x[(size_t)row0 * DD + idx];
    }
    __syncthreads();

    float acc[8][4];
    float4 wb4 = *(const float4*)&Wb[tx * 4];
    #pragma unroll
    for (int i = 0; i < 8; i++) { acc[i][0]=wb4.x; acc[i][1]=wb4.y; acc[i][2]=wb4.z; acc[i][3]=wb4.w; }
    for (int f = 0; f < 128; f++) {
        float4 w = *(const float4*)&g_WwT[f * DD + tx * 4];
        #pragma unroll
        for (int i = 0; i < 8; i++) {
            float xv = sX[(ty * 8 + i) * 128 + f];
            acc[i][0] += xv * w.x; acc[i][1] += xv * w.y;
            acc[i][2] += xv * w.z; acc[i][3] += xv * w.w;
        }
    }
    __syncthreads();
    #pragma unroll
    for (int i = 0; i < 8; i++) {
        int r = ty * 8 + i;
        float4 v; v.x = acc[i][0]; v.y = acc[i][1]; v.z = acc[i][2]; v.w = acc[i][3];
        *(float4*)&g_h[(size_t)(row0 + r) * DD + tx * 4] = v;
        *(float4*)&sX[r * 128 + tx * 4] = v;
    }
    __syncthreads();

    float acc2[8][4];
    #pragma unroll
    for (int i = 0; i < 8; i++) { acc2[i][0]=0.f; acc2[i][1]=0.f; acc2[i][2]=0.f; acc2[i][3]=0.f; }
    for (int f = 0; f < 128; f++) {
        float4 m4 = *(const float4*)&g_M[f * DD + tx * 4];
        #pragma unroll
        for (int i = 0; i < 8; i++) {
            float hv = sX[(ty * 8 + i) * 128 + f];
            acc2[i][0] += hv * m4.x; acc2[i][1] += hv * m4.y;
            acc2[i][2] += hv * m4.z; acc2[i][3] += hv * m4.w;
        }
    }
    #pragma unroll
    for (int i = 0; i < 8; i++) {
        float4 v; v.x = acc2[i][0]; v.y = acc2[i][1]; v.z = acc2[i][2]; v.w = acc2[i][3];
        *(float4*)&g_g[(size_t)(row0 + ty * 8 + i) * DD + tx * 4] = v;
    }
}

// ---------------- K3: e_sym = g @ h^T (single GEMM); exp+mask+colsum fused ----------------
#define LDT 33
#define SMEM_K3 (128 * 129 * 4)   // 66048 B: transpose buffer dominates
__global__ __launch_bounds__(256) void k_scores(const float* __restrict__ adj) {
    extern __shared__ float sm[];
    float* sG = sm;                 // 128 x LDT
    float* sH = sm + 128 * LDT;     // 128 x LDT

    int u = blockIdx.x, b = blockIdx.y;
    int tj = 0, rem = u;
    while (rem >= 8 - tj) { rem -= 8 - tj; tj++; }
    int tk = tj + rem;
    int j0 = tj * 128, k0 = tk * 128;

    int t = threadIdx.x, tx = t & 15, ty = t >> 4;
    const float* Hb = g_h + (size_t)b * NN * DD;
    const float* Gb = g_g + (size_t)b * NN * DD;

    float acc[8][8];
    #pragma unroll
    for (int i = 0; i < 8; i++)
        #pragma unroll
        for (int j = 0; j < 8; j++) acc[i][j] = 0.f;

    for (int ch = 0; ch < 4; ch++) {
        int c = t & 31, r0 = t >> 5;
        #pragma unroll
        for (int i = 0; i < 16; i++) {
            int r = r0 + 8 * i;
            sG[r * LDT + c] = Gb[(size_t)(j0 + r) * DD + ch * 32 + c];
            sH[r * LDT + c] = Hb[(size_t)(k0 + r) * DD + ch * 32 + c];
        }
        __syncthreads();
        for (int kk = 0; kk < 32; kk++) {
            float a[8], bb[8];
            #pragma unroll
            for (int i = 0; i < 8; i++) {
                a[i]  = sG[(ty * 8 + i) * LDT + kk];
                bb[i] = sH[(tx * 8 + i) * LDT + kk];
            }
            #pragma unroll
            for (int i = 0; i < 8; i++)
                #pragma unroll
                for (int j = 0; j < 8; j++)
                    acc[i][j] += a[i] * bb[j];
        }
        __syncthreads();
    }

    const float* adjb = adj + (size_t)b * NN * NN;
    float* scb = g_scores + (size_t)b * NN * NN;

    // ---- direct tile: exp + mask + write + column partials ----
    float colp[8];
    #pragma unroll
    for (int jj = 0; jj < 8; jj++) colp[jj] = 0.f;

    #pragma unroll
    for (int i = 0; i < 8; i++) {
        int j = j0 + ty * 8 + i;
        #pragma unroll
        for (int jj = 0; jj < 8; jj += 4) {
            int k = k0 + tx * 8 + jj;
            float4 am = *(const float4*)&adjb[(size_t)j * NN + k];
            float4 v;
            v.x = am.x > 0.f ? __expf(acc[i][jj + 0]) : 0.f;
            v.y = am.y > 0.f ? __expf(acc[i][jj + 1]) : 0.f;
            v.z = am.z > 0.f ? __expf(acc[i][jj + 2]) : 0.f;
            v.w = am.w > 0.f ? __expf(acc[i][jj + 3]) : 0.f;
            colp[jj + 0] += am.x > 0.f ? v.x : 1.f;
            colp[jj + 1] += am.y > 0.f ? v.y : 1.f;
            colp[jj + 2] += am.z > 0.f ? v.z : 1.f;
            colp[jj + 3] += am.w > 0.f ? v.w : 1.f;
            *(float4*)&scb[(size_t)j * NN + k] = v;
        }
    }

    // reduce column partials across 16 ty-groups, one atomic per column
    float* sC = sm;   // 16 x 128 floats
    #pragma unroll
    for (int jj = 0; jj < 8; jj++)
        sC[ty * 128 + tx * 8 + jj] = colp[jj];
    __syncthreads();
    if (t < 128) {
        float z = 0.f;
        #pragma unroll
        for (int q = 0; q < 16; q++) z += sC[q * 128 + t];
        atomicAdd(&g_z[b * NN + k0 + t], z);
    }

    // ---- mirrored tile: smem transpose, exp + mask + colsum ----
    if (tj != tk) {
        __syncthreads();
        float* sT = sm;   // 128 x 129 floats (fits 66048 B)
        #pragma unroll
        for (int i = 0; i < 8; i++)
            #pragma unroll
            for (int jj = 0; jj < 8; jj++)
                sT[(tx * 8 + jj) * 129 + (ty * 8 + i)] = acc[i][jj];
        __syncthreads();
        int c = t & 127, r0b = t >> 7;
        float zM = 0.f;
        #pragma unroll 4
        for (int p = 0; p < 64; p++) {
            int r = r0b + 2 * p;
            int k = k0 + r, j = j0 + c;
            float am = adjb[(size_t)k * NN + j];
            float ev = am > 0.f ? __expf(sT[r * 129 + c]) : 0.f;
            zM += am > 0.f ? ev : 1.f;
            scb[(size_t)k * NN + j] = ev;
        }
        atomicAdd(&g_z[b * NN + j0 + c], zM);
    }
}

// ---------------- K4: invert denominators ----------------
__global__ void k_invz() {
    int i = blockIdx.x * 256 + threadIdx.x;
    g_rz[i] = 1.0f / g_z[i];
}

// ---------------- K5: h_prime = relu( (n * rz_col) @ h ) ----------------
__global__ __launch_bounds__(256) void k_hprime() {
    __shared__ float sA[64 * 33];
    __shared__ float sH[32 * 128];
    int b = blockIdx.y, i0 = blockIdx.x * 64;
    int t = threadIdx.x, tx = t & 31, ty = t >> 5;
    const float* scb = g_scores + (size_t)b * NN * NN;
    const float* Hb  = g_h      + (size_t)b * NN * DD;
    const float* rzb = g_rz     + b * NN;

    float acc[8][4];
    #pragma unroll
    for (int i = 0; i < 8; i++) { acc[i][0]=0.f; acc[i][1]=0.f; acc[i][2]=0.f; acc[i][3]=0.f; }

    for (int ch = 0; ch < 32; ch++) {
        int jbase = ch * 32;
        {
            int c = t & 31, r0 = t >> 5;
            float rz = rzb[jbase + c];
            #pragma unroll
            for (int p = 0; p < 8; p++) {
                int r = r0 + 8 * p;
                sA[r * 33 + c] = scb[(size_t)(i0 + r) * NN + jbase + c] * rz;
            }
        }
        {
            int c2 = t & 127, r0b = t >> 7;
            #pragma unroll
            for (int p = 0; p < 16; p++) {
                int r = r0b + 2 * p;
                sH[r * 128 + c2] = Hb[(size_t)(jbase + r) * DD + c2];
            }
        }
        __syncthreads();
        for (int kk = 0; kk < 32; kk++) {
            float4 hv = *(const float4*)&sH[kk * 128 + tx * 4];
            #pragma unroll
            for (int i = 0; i < 8; i++) {
                float a = sA[(ty * 8 + i) * 33 + kk];
                acc[i][0] += a * hv.x; acc[i][1] += a * hv.y;
                acc[i][2] += a * hv.z; acc[i][3] += a * hv.w;
            }
        }
        __syncthreads();
    }
    float* hpb = g_hp + (size_t)b * NN * DD;
    #pragma unroll
    for (int i = 0; i < 8; i++) {
        float4 v;
        v.x = fmaxf(acc[i][0], 0.f); v.y = fmaxf(acc[i][1], 0.f);
        v.z = fmaxf(acc[i][2], 0.f); v.w = fmaxf(acc[i][3], 0.f);
        *(float4*)&hpb[(size_t)(i0 + ty * 8 + i) * DD + tx * 4] = v;
    }
}

// ---------------- K6: gates + output ----------------
__global__ __launch_bounds__(256) void k_out(const float* __restrict__ x,
        const float* __restrict__ wi_u, const float* __restrict__ wi_x,
        const float* __restrict__ wf_u, const float* __restrict__ wf_x,
        const float* __restrict__ wo_u, const float* __restrict__ wo_x,
        float* __restrict__ out) {
    int node = blockIdx.x * 8 + (threadIdx.x >> 5);
    int lane = threadIdx.x & 31;
    size_t base = (size_t)node * DD;
    float hp4[4], x4[4];
    float si = 0.f, sf = 0.f, so = 0.f;
    #pragma unroll
    for (int i = 0; i < 4; i++) {
        int d = lane + 32 * i;
        hp4[i] = g_hp[base + d];
        x4[i]  = x[base + d];
        si += hp4[i] * wi_u[d] + x4[i] * wi_x[d];
        sf += hp4[i] * wf_u[d] + x4[i] * wf_x[d];
        so += hp4[i] * wo_u[d] + x4[i] * wo_x[d];
    }
    #pragma unroll
    for (int off = 16; off; off >>= 1) {
        si += __shfl_xor_sync(0xffffffffu, si, off);
        sf += __shfl_xor_sync(0xffffffffu, sf, off);
        so += __shfl_xor_sync(0xffffffffu, so, off);
    }
    float ic = 1.f / (1.f + __expf(-si));
    float fc = 1.f / (1.f + __expf(-sf));
    float oc = 1.f / (1.f + __expf(-so));
    #pragma unroll
    for (int i = 0; i < 4; i++) {
        int d = lane + 32 * i;
        out[base + d] = oc * tanhf(ic * hp4[i] + fc * x4[i]);
    }
}

// ---------------- launch ----------------
extern "C" void kernel_launch(void* const* d_in, const int* in_sizes, int n_in,
                              void* d_out, int out_size) {
    const float* x    = (const float*)d_in[0];
    const float* adj  = (const float*)d_in[1];
    const float* Ww   = (const float*)d_in[2];
    const float* Wb   = (const float*)d_in[3];
    const float* A    = (const float*)d_in[4];
    const float* wi_u = (const float*)d_in[5];
    const float* wi_x = (const float*)d_in[6];
    const float* wf_u = (const float*)d_in[7];
    const float* wf_x = (const float*)d_in[8];
    const float* wo_u = (const float*)d_in[9];
    const float* wo_x = (const float*)d_in[10];
    float* out = (float*)d_out;

    cudaFuncSetAttribute(k_scores, cudaFuncAttributeMaxDynamicSharedMemorySize, SMEM_K3);

    k_prep<<<64, 256>>>(Ww, A);
    k_h_g<<<BN / 64, 256>>>(x, Wb);
    k_scores<<<dim3(36, BB), 256, SMEM_K3>>>(adj);
    k_invz<<<64, 256>>>();
    k_hprime<<<dim3(NN / 64, BB), 256>>>();
    k_out<<<BN / 8, 256>>>(x, wi_u, wi_x, wf_u, wf_x, wo_u, wo_x, out);
}

// round 4
// speedup vs baseline: 1.6069x; 1.2153x over previous
#include <cuda_runtime.h>
#include <cstdint>

#define BB 16
#define NN 1024
#define DD 128
#define BN (BB*NN)

// ---------------- packed fp32x2 helpers (sm_103a) ----------------
__device__ __forceinline__ uint64_t pack2(float lo, float hi) {
    uint64_t p; asm("mov.b64 %0, {%1, %2};" : "=l"(p) : "f"(lo), "f"(hi)); return p;
}
__device__ __forceinline__ void ffma2(uint64_t& d, uint64_t a, uint64_t b) {
    asm("fma.rn.f32x2 %0, %1, %2, %0;" : "+l"(d) : "l"(a), "l"(b));
}
__device__ __forceinline__ float2 unpack2(uint64_t p) {
    float2 v; asm("mov.b64 {%0, %1}, %2;" : "=f"(v.x), "=f"(v.y) : "l"(p)); return v;
}

// ---------------- scratch ----------------
__device__ float g_WwT[DD*DD];
__device__ float g_M  [DD*DD];               // A + A^T
__device__ float g_h  [BN*DD];
__device__ float g_g  [BN*DD];               // g = h @ (A+A^T)
__device__ float g_scores[(size_t)BB*NN*NN]; // exp'd masked numerators
__device__ float g_z  [BB*NN];
__device__ float g_hp [BN*DD];

// ---------------- K0: transpose Ww, form M = A+A^T, zero g_z ----------------
__global__ void k_prep(const float* __restrict__ Ww, const float* __restrict__ A) {
    int i = blockIdx.x * 256 + threadIdx.x;   // 16384 == DD*DD == BB*NN
    int d = i >> 7, f = i & 127;
    g_WwT[f * DD + d] = Ww[d * DD + f];
    g_M[d * DD + f] = A[d * DD + f] + A[f * DD + d];
    g_z[i] = 0.f;
}

// ---------------- K1: fused h = x@Ww^T + Wb ; g = h@M ----------------
__global__ __launch_bounds__(256) void k_h_g(const float* __restrict__ x,
                                             const float* __restrict__ Wb) {
    __shared__ float sX[64 * 128];
    int t = threadIdx.x;
    int tx = t & 31, ty = t >> 5;
    int row0 = blockIdx.x * 64;

    #pragma unroll
    for (int i = 0; i < 32; i++) {
        int idx = i * 256 + t;
        sX[idx] = x[(size_t)row0 * DD + idx];
    }
    __syncthreads();

    float acc[8][4];
    float4 wb4 = *(const float4*)&Wb[tx * 4];
    #pragma unroll
    for (int i = 0; i < 8; i++) { acc[i][0]=wb4.x; acc[i][1]=wb4.y; acc[i][2]=wb4.z; acc[i][3]=wb4.w; }
    for (int f = 0; f < 128; f++) {
        float4 w = *(const float4*)&g_WwT[f * DD + tx * 4];
        #pragma unroll
        for (int i = 0; i < 8; i++) {
            float xv = sX[(ty * 8 + i) * 128 + f];
            acc[i][0] += xv * w.x; acc[i][1] += xv * w.y;
            acc[i][2] += xv * w.z; acc[i][3] += xv * w.w;
        }
    }
    __syncthreads();
    #pragma unroll
    for (int i = 0; i < 8; i++) {
        int r = ty * 8 + i;
        float4 v; v.x = acc[i][0]; v.y = acc[i][1]; v.z = acc[i][2]; v.w = acc[i][3];
        *(float4*)&g_h[(size_t)(row0 + r) * DD + tx * 4] = v;
        *(float4*)&sX[r * 128 + tx * 4] = v;
    }
    __syncthreads();

    float acc2[8][4];
    #pragma unroll
    for (int i = 0; i < 8; i++) { acc2[i][0]=0.f; acc2[i][1]=0.f; acc2[i][2]=0.f; acc2[i][3]=0.f; }
    for (int f = 0; f < 128; f++) {
        float4 m4 = *(const float4*)&g_M[f * DD + tx * 4];
        #pragma unroll
        for (int i = 0; i < 8; i++) {
            float hv = sX[(ty * 8 + i) * 128 + f];
            acc2[i][0] += hv * m4.x; acc2[i][1] += hv * m4.y;
            acc2[i][2] += hv * m4.z; acc2[i][3] += hv * m4.w;
        }
    }
    #pragma unroll
    for (int i = 0; i < 8; i++) {
        float4 v; v.x = acc2[i][0]; v.y = acc2[i][1]; v.z = acc2[i][2]; v.w = acc2[i][3];
        *(float4*)&g_g[(size_t)(row0 + ty * 8 + i) * DD + tx * 4] = v;
    }
}

// ---------------- K3: e_sym = g @ h^T (f32x2 packed); exp+mask+colsum fused ----------------
#define LDT 33
#define LDH 130                   // transposed h tile pad: even (8B align) + conflict-safe
#define SMEM_K3 (128 * 129 * 4)   // 66048 B: transpose buffer dominates
__global__ __launch_bounds__(256) void k_scores(const float* __restrict__ adj) {
    extern __shared__ float sm[];
    float* sG  = sm;                   // 128 x LDT  (row-major, broadcast A reads)
    float* sHT = sm + 128 * LDT;       // 32 x LDH   (k-major: pairs contiguous)

    int u = blockIdx.x, b = blockIdx.y;
    int tj = 0, rem = u;
    while (rem >= 8 - tj) { rem -= 8 - tj; tj++; }
    int tk = tj + rem;
    int j0 = tj * 128, k0 = tk * 128;

    int t = threadIdx.x, tx = t & 15, ty = t >> 4;
    const float* Hb = g_h + (size_t)b * NN * DD;
    const float* Gb = g_g + (size_t)b * NN * DD;

    uint64_t accp[8][4];
    #pragma unroll
    for (int i = 0; i < 8; i++)
        #pragma unroll
        for (int j = 0; j < 4; j++) accp[i][j] = 0ull;

    for (int ch = 0; ch < 4; ch++) {
        int c = t & 31, r0 = t >> 5;
        #pragma unroll
        for (int i = 0; i < 16; i++) {
            int r = r0 + 8 * i;
            sG [r * LDT + c] = Gb[(size_t)(j0 + r) * DD + ch * 32 + c];
            sHT[c * LDH + r] = Hb[(size_t)(k0 + r) * DD + ch * 32 + c];
        }
        __syncthreads();
        for (int kk = 0; kk < 32; kk++) {
            uint64_t bp[4];
            #pragma unroll
            for (int jj = 0; jj < 4; jj++)
                bp[jj] = *(const uint64_t*)&sHT[kk * LDH + tx * 8 + jj * 2];
            #pragma unroll
            for (int i = 0; i < 8; i++) {
                float av = sG[(ty * 8 + i) * LDT + kk];
                uint64_t ap = pack2(av, av);
                #pragma unroll
                for (int jj = 0; jj < 4; jj++)
                    ffma2(accp[i][jj], ap, bp[jj]);
            }
        }
        __syncthreads();
    }

    // unpack to scalar tile
    float acc[8][8];
    #pragma unroll
    for (int i = 0; i < 8; i++)
        #pragma unroll
        for (int jj = 0; jj < 4; jj++) {
            float2 v = unpack2(accp[i][jj]);
            acc[i][2 * jj] = v.x; acc[i][2 * jj + 1] = v.y;
        }

    const float* adjb = adj + (size_t)b * NN * NN;
    float* scb = g_scores + (size_t)b * NN * NN;

    // ---- direct tile: exp + mask + write + column partials ----
    float colp[8];
    #pragma unroll
    for (int jj = 0; jj < 8; jj++) colp[jj] = 0.f;

    #pragma unroll
    for (int i = 0; i < 8; i++) {
        int j = j0 + ty * 8 + i;
        #pragma unroll
        for (int jj = 0; jj < 8; jj += 4) {
            int k = k0 + tx * 8 + jj;
            float4 am = *(const float4*)&adjb[(size_t)j * NN + k];
            float4 v;
            v.x = am.x > 0.f ? __expf(acc[i][jj + 0]) : 0.f;
            v.y = am.y > 0.f ? __expf(acc[i][jj + 1]) : 0.f;
            v.z = am.z > 0.f ? __expf(acc[i][jj + 2]) : 0.f;
            v.w = am.w > 0.f ? __expf(acc[i][jj + 3]) : 0.f;
            colp[jj + 0] += am.x > 0.f ? v.x : 1.f;
            colp[jj + 1] += am.y > 0.f ? v.y : 1.f;
            colp[jj + 2] += am.z > 0.f ? v.z : 1.f;
            colp[jj + 3] += am.w > 0.f ? v.w : 1.f;
            *(float4*)&scb[(size_t)j * NN + k] = v;
        }
    }

    // reduce column partials across 16 ty-groups, one atomic per column
    float* sC = sm;   // 16 x 128 floats
    __syncthreads();
    #pragma unroll
    for (int jj = 0; jj < 8; jj++)
        sC[ty * 128 + tx * 8 + jj] = colp[jj];
    __syncthreads();
    if (t < 128) {
        float z = 0.f;
        #pragma unroll
        for (int q = 0; q < 16; q++) z += sC[q * 128 + t];
        atomicAdd(&g_z[b * NN + k0 + t], z);
    }

    // ---- mirrored tile: smem transpose, exp + mask + colsum ----
    if (tj != tk) {
        __syncthreads();
        float* sT = sm;   // 128 x 129 floats
        #pragma unroll
        for (int i = 0; i < 8; i++)
            #pragma unroll
            for (int jj = 0; jj < 8; jj++)
                sT[(tx * 8 + jj) * 129 + (ty * 8 + i)] = acc[i][jj];
        __syncthreads();
        int c = t & 127, r0b = t >> 7;
        float zM = 0.f;
        #pragma unroll 4
        for (int p = 0; p < 64; p++) {
            int r = r0b + 2 * p;
            int k = k0 + r, j = j0 + c;
            float am = adjb[(size_t)k * NN + j];
            float ev = am > 0.f ? __expf(sT[r * 129 + c]) : 0.f;
            zM += am > 0.f ? ev : 1.f;
            scb[(size_t)k * NN + j] = ev;
        }
        atomicAdd(&g_z[b * NN + j0 + c], zM);
    }
}

// ---------------- K5: h_prime = relu( (n / z_col) @ h ), f32x2 packed ----------------
__global__ __launch_bounds__(256) void k_hprime() {
    __shared__ float sA[64 * 33];
    __shared__ float sH[32 * 128];
    int b = blockIdx.y, i0 = blockIdx.x * 64;
    int t = threadIdx.x, tx = t & 31, ty = t >> 5;
    const float* scb = g_scores + (size_t)b * NN * NN;
    const float* Hb  = g_h      + (size_t)b * NN * DD;
    const float* zb  = g_z      + b * NN;

    uint64_t accp[8][2];
    #pragma unroll
    for (int i = 0; i < 8; i++) { accp[i][0] = 0ull; accp[i][1] = 0ull; }

    for (int ch = 0; ch < 32; ch++) {
        int jbase = ch * 32;
        {
            int c = t & 31, r0 = t >> 5;
            float rz = __fdividef(1.0f, zb[jbase + c]);
            #pragma unroll
            for (int p = 0; p < 8; p++) {
                int r = r0 + 8 * p;
                sA[r * 33 + c] = scb[(size_t)(i0 + r) * NN + jbase + c] * rz;
            }
        }
        {
            int c2 = t & 127, r0b = t >> 7;
            #pragma unroll
            for (int p = 0; p < 16; p++) {
                int r = r0b + 2 * p;
                sH[r * 128 + c2] = Hb[(size_t)(jbase + r) * DD + c2];
            }
        }
        __syncthreads();
        for (int kk = 0; kk < 32; kk++) {
            uint64_t h01 = *(const uint64_t*)&sH[kk * 128 + tx * 4];
            uint64_t h23 = *(const uint64_t*)&sH[kk * 128 + tx * 4 + 2];
            #pragma unroll
            for (int i = 0; i < 8; i++) {
                float a = sA[(ty * 8 + i) * 33 + kk];
                uint64_t ap = pack2(a, a);
                ffma2(accp[i][0], ap, h01);
                ffma2(accp[i][1], ap, h23);
            }
        }
        __syncthreads();
    }
    float* hpb = g_hp + (size_t)b * NN * DD;
    #pragma unroll
    for (int i = 0; i < 8; i++) {
        float2 v01 = unpack2(accp[i][0]);
        float2 v23 = unpack2(accp[i][1]);
        float4 v;
        v.x = fmaxf(v01.x, 0.f); v.y = fmaxf(v01.y, 0.f);
        v.z = fmaxf(v23.x, 0.f); v.w = fmaxf(v23.y, 0.f);
        *(float4*)&hpb[(size_t)(i0 + ty * 8 + i) * DD + tx * 4] = v;
    }
}

// ---------------- K6: gates + output ----------------
__global__ __launch_bounds__(256) void k_out(const float* __restrict__ x,
        const float* __restrict__ wi_u, const float* __restrict__ wi_x,
        const float* __restrict__ wf_u, const float* __restrict__ wf_x,
        const float* __restrict__ wo_u, const float* __restrict__ wo_x,
        float* __restrict__ out) {
    int node = blockIdx.x * 8 + (threadIdx.x >> 5);
    int lane = threadIdx.x & 31;
    size_t base = (size_t)node * DD;
    float hp4[4], x4[4];
    float si = 0.f, sf = 0.f, so = 0.f;
    #pragma unroll
    for (int i = 0; i < 4; i++) {
        int d = lane + 32 * i;
        hp4[i] = g_hp[base + d];
        x4[i]  = x[base + d];
        si += hp4[i] * wi_u[d] + x4[i] * wi_x[d];
        sf += hp4[i] * wf_u[d] + x4[i] * wf_x[d];
        so += hp4[i] * wo_u[d] + x4[i] * wo_x[d];
    }
    #pragma unroll
    for (int off = 16; off; off >>= 1) {
        si += __shfl_xor_sync(0xffffffffu, si, off);
        sf += __shfl_xor_sync(0xffffffffu, sf, off);
        so += __shfl_xor_sync(0xffffffffu, so, off);
    }
    float ic = 1.f / (1.f + __expf(-si));
    float fc = 1.f / (1.f + __expf(-sf));
    float oc = 1.f / (1.f + __expf(-so));
    #pragma unroll
    for (int i = 0; i < 4; i++) {
        int d = lane + 32 * i;
        out[base + d] = oc * tanhf(ic * hp4[i] + fc * x4[i]);
    }
}

// ---------------- launch ----------------
extern "C" void kernel_launch(void* const* d_in, const int* in_sizes, int n_in,
                              void* d_out, int out_size) {
    const float* x    = (const float*)d_in[0];
    const float* adj  = (const float*)d_in[1];
    const float* Ww   = (const float*)d_in[2];
    const float* Wb   = (const float*)d_in[3];
    const float* A    = (const float*)d_in[4];
    const float* wi_u = (const float*)d_in[5];
    const float* wi_x = (const float*)d_in[6];
    const float* wf_u = (const float*)d_in[7];
    const float* wf_x = (const float*)d_in[8];
    const float* wo_u = (const float*)d_in[9];
    const float* wo_x = (const float*)d_in[10];
    float* out = (float*)d_out;

    cudaFuncSetAttribute(k_scores, cudaFuncAttributeMaxDynamicSharedMemorySize, SMEM_K3);

    k_prep<<<64, 256>>>(Ww, A);
    k_h_g<<<BN / 64, 256>>>(x, Wb);
    k_scores<<<dim3(36, BB), 256, SMEM_K3>>>(adj);
    k_hprime<<<dim3(NN / 64, BB), 256>>>();
    k_out<<<BN / 8, 256>>>(x, wi_u, wi_x, wf_u, wf_x, wo_u, wo_x, out);
}

// round 5
// speedup vs baseline: 1.6985x; 1.0570x over previous
#include <cuda_runtime.h>
#include <cstdint>

#define BB 16
#define NN 1024
#define DD 128
#define BN (BB*NN)

// ---------------- packed fp32x2 helpers (sm_103a) ----------------
__device__ __forceinline__ void ffma2(uint64_t& d, uint64_t a, uint64_t b) {
    asm("fma.rn.f32x2 %0, %1, %2, %0;" : "+l"(d) : "l"(a), "l"(b));
}
__device__ __forceinline__ float2 unpack2(uint64_t p) {
    float2 v; asm("mov.b64 {%0, %1}, %2;" : "=f"(v.x), "=f"(v.y) : "l"(p)); return v;
}

// ---------------- scratch ----------------
__device__ float g_WwT[DD*DD];
__device__ float g_M  [DD*DD];               // A + A^T
__device__ float g_h  [BN*DD];
__device__ float g_g  [BN*DD];               // g = h @ (A+A^T)
__device__ float g_scores[(size_t)BB*NN*NN]; // exp'd masked numerators
__device__ float g_z  [BB*NN];
__device__ float g_hp [BN*DD];

// ---------------- K0: transpose Ww, form M = A+A^T, zero g_z ----------------
__global__ void k_prep(const float* __restrict__ Ww, const float* __restrict__ A) {
    int i = blockIdx.x * 256 + threadIdx.x;   // 16384 == DD*DD == BB*NN
    int d = i >> 7, f = i & 127;
    g_WwT[f * DD + d] = Ww[d * DD + f];
    g_M[d * DD + f] = A[d * DD + f] + A[f * DD + d];
    g_z[i] = 0.f;
}

// ---------------- K1: fused h = x@Ww^T + Wb ; g = h@M ----------------
__global__ __launch_bounds__(256) void k_h_g(const float* __restrict__ x,
                                             const float* __restrict__ Wb) {
    __shared__ float sX[64 * 128];
    int t = threadIdx.x;
    int tx = t & 31, ty = t >> 5;
    int row0 = blockIdx.x * 64;

    #pragma unroll
    for (int i = 0; i < 32; i++) {
        int idx = i * 256 + t;
        sX[idx] = x[(size_t)row0 * DD + idx];
    }
    __syncthreads();

    float acc[8][4];
    float4 wb4 = *(const float4*)&Wb[tx * 4];
    #pragma unroll
    for (int i = 0; i < 8; i++) { acc[i][0]=wb4.x; acc[i][1]=wb4.y; acc[i][2]=wb4.z; acc[i][3]=wb4.w; }
    for (int f = 0; f < 128; f++) {
        float4 w = *(const float4*)&g_WwT[f * DD + tx * 4];
        #pragma unroll
        for (int i = 0; i < 8; i++) {
            float xv = sX[(ty * 8 + i) * 128 + f];
            acc[i][0] += xv * w.x; acc[i][1] += xv * w.y;
            acc[i][2] += xv * w.z; acc[i][3] += xv * w.w;
        }
    }
    __syncthreads();
    #pragma unroll
    for (int i = 0; i < 8; i++) {
        int r = ty * 8 + i;
        float4 v; v.x = acc[i][0]; v.y = acc[i][1]; v.z = acc[i][2]; v.w = acc[i][3];
        *(float4*)&g_h[(size_t)(row0 + r) * DD + tx * 4] = v;
        *(float4*)&sX[r * 128 + tx * 4] = v;
    }
    __syncthreads();

    float acc2[8][4];
    #pragma unroll
    for (int i = 0; i < 8; i++) { acc2[i][0]=0.f; acc2[i][1]=0.f; acc2[i][2]=0.f; acc2[i][3]=0.f; }
    for (int f = 0; f < 128; f++) {
        float4 m4 = *(const float4*)&g_M[f * DD + tx * 4];
        #pragma unroll
        for (int i = 0; i < 8; i++) {
            float hv = sX[(ty * 8 + i) * 128 + f];
            acc2[i][0] += hv * m4.x; acc2[i][1] += hv * m4.y;
            acc2[i][2] += hv * m4.z; acc2[i][3] += hv * m4.w;
        }
    }
    #pragma unroll
    for (int i = 0; i < 8; i++) {
        float4 v; v.x = acc2[i][0]; v.y = acc2[i][1]; v.z = acc2[i][2]; v.w = acc2[i][3];
        *(float4*)&g_g[(size_t)(row0 + ty * 8 + i) * DD + tx * 4] = v;
    }
}

// ---------------- K3: e_sym = g @ h^T ; exp+mask+colsum fused ----------------
// A-operand: duplicated float2 pairs (broadcast LDS.64, no packs).
// B-operand: h transposed [feature][k-row], thread tx owns k-cols {jj*32+tx*2, +1}
//            -> each LDS.64 is 16 lanes x 8B contiguous = conflict-free.
#define SMEM_K3 (128 * 129 * 4)   // 66048 B (transpose buffer dominates the union)
__global__ __launch_bounds__(256) void k_scores(const float* __restrict__ adj) {
    extern __shared__ float sm[];
    float2* sG2 = (float2*)sm;                 // 128 x 33 float2 (dup pairs) = 8448 floats
    float*  sHT = sm + 128 * 33 * 2;           // 32 x 130 floats

    int u = blockIdx.x, b = blockIdx.y;
    int tj = 0, rem = u;
    while (rem >= 8 - tj) { rem -= 8 - tj; tj++; }
    int tk = tj + rem;
    int j0 = tj * 128, k0 = tk * 128;

    int t = threadIdx.x, tx = t & 15, ty = t >> 4;
    const float* Hb = g_h + (size_t)b * NN * DD;
    const float* Gb = g_g + (size_t)b * NN * DD;

    uint64_t accp[8][4];
    #pragma unroll
    for (int i = 0; i < 8; i++)
        #pragma unroll
        for (int j = 0; j < 4; j++) accp[i][j] = 0ull;

    for (int ch = 0; ch < 4; ch++) {
        int c = t & 31, r0 = t >> 5;
        #pragma unroll
        for (int i = 0; i < 16; i++) {
            int r = r0 + 8 * i;
            float gv = Gb[(size_t)(j0 + r) * DD + ch * 32 + c];
            sG2[r * 33 + c] = make_float2(gv, gv);
            sHT[c * 130 + r] = Hb[(size_t)(k0 + r) * DD + ch * 32 + c];
        }
        __syncthreads();
        for (int kk = 0; kk < 32; kk++) {
            uint64_t bp[4];
            #pragma unroll
            for (int jj = 0; jj < 4; jj++)
                bp[jj] = *(const uint64_t*)&sHT[kk * 130 + jj * 32 + tx * 2];
            #pragma unroll
            for (int i = 0; i < 8; i++) {
                uint64_t ap = *(const uint64_t*)&sG2[(ty * 8 + i) * 33 + kk];
                #pragma unroll
                for (int jj = 0; jj < 4; jj++)
                    ffma2(accp[i][jj], ap, bp[jj]);
            }
        }
        __syncthreads();
    }

    // unpack to scalar tile: acc[i][2*jj+e] -> k-col = jj*32 + tx*2 + e
    float acc[8][8];
    #pragma unroll
    for (int i = 0; i < 8; i++)
        #pragma unroll
        for (int jj = 0; jj < 4; jj++) {
            float2 v = unpack2(accp[i][jj]);
            acc[i][2 * jj] = v.x; acc[i][2 * jj + 1] = v.y;
        }

    const float* adjb = adj + (size_t)b * NN * NN;
    float* scb = g_scores + (size_t)b * NN * NN;

    // ---- direct tile: exp + mask + write + column partials ----
    float colp[8];
    #pragma unroll
    for (int jj = 0; jj < 8; jj++) colp[jj] = 0.f;

    #pragma unroll
    for (int i = 0; i < 8; i++) {
        int j = j0 + ty * 8 + i;
        #pragma unroll
        for (int jj = 0; jj < 4; jj++) {
            int k = k0 + jj * 32 + tx * 2;
            float2 am = *(const float2*)&adjb[(size_t)j * NN + k];
            float2 v;
            v.x = am.x > 0.f ? __expf(acc[i][2 * jj + 0]) : 0.f;
            v.y = am.y > 0.f ? __expf(acc[i][2 * jj + 1]) : 0.f;
            colp[2 * jj + 0] += am.x > 0.f ? v.x : 1.f;
            colp[2 * jj + 1] += am.y > 0.f ? v.y : 1.f;
            *(float2*)&scb[(size_t)j * NN + k] = v;
        }
    }

    // reduce column partials across 16 ty-groups, one atomic per column
    float* sC = sm;   // 16 x 128 floats
    __syncthreads();
    #pragma unroll
    for (int jj = 0; jj < 4; jj++) {
        sC[ty * 128 + jj * 32 + tx * 2 + 0] = colp[2 * jj + 0];
        sC[ty * 128 + jj * 32 + tx * 2 + 1] = colp[2 * jj + 1];
    }
    __syncthreads();
    if (t < 128) {
        float z = 0.f;
        #pragma unroll
        for (int q = 0; q < 16; q++) z += sC[q * 128 + t];
        atomicAdd(&g_z[b * NN + k0 + t], z);
    }

    // ---- mirrored tile: smem transpose, exp + mask + colsum ----
    if (tj != tk) {
        __syncthreads();
        float* sT = sm;   // 128 x 129 floats
        #pragma unroll
        for (int i = 0; i < 8; i++)
            #pragma unroll
            for (int jj = 0; jj < 4; jj++) {
                sT[(jj * 32 + tx * 2 + 0) * 129 + (ty * 8 + i)] = acc[i][2 * jj + 0];
                sT[(jj * 32 + tx * 2 + 1) * 129 + (ty * 8 + i)] = acc[i][2 * jj + 1];
            }
        __syncthreads();
        int c = t & 127, r0b = t >> 7;
        float zM = 0.f;
        #pragma unroll 4
        for (int p = 0; p < 64; p++) {
            int r = r0b + 2 * p;
            int k = k0 + r, j = j0 + c;
            float am = adjb[(size_t)k * NN + j];
            float ev = am > 0.f ? __expf(sT[r * 129 + c]) : 0.f;
            zM += am > 0.f ? ev : 1.f;
            scb[(size_t)k * NN + j] = ev;
        }
        atomicAdd(&g_z[b * NN + j0 + c], zM);
    }
}

// ---------------- K5: h_prime = relu( (n / z_col) @ h ) ----------------
// 64 x 128 tile, 128 threads, 8x8 micro-tile, dup-a pairs, conflict-free b.
__global__ __launch_bounds__(128) void k_hprime() {
    __shared__ float2 sA2[64 * 33];   // dup pairs
    __shared__ float  sH [32 * 130];
    int b = blockIdx.y, i0 = blockIdx.x * 64;
    int t = threadIdx.x, tx = t & 15, ty = t >> 4;   // ty 0..7
    const float* scb = g_scores + (size_t)b * NN * NN;
    const float* Hb  = g_h      + (size_t)b * NN * DD;
    const float* zb  = g_z      + b * NN;

    uint64_t accp[8][4];
    #pragma unroll
    for (int i = 0; i < 8; i++)
        #pragma unroll
        for (int jj = 0; jj < 4; jj++) accp[i][jj] = 0ull;

    for (int ch = 0; ch < 32; ch++) {
        int jbase = ch * 32;
        {   // attention tile 64x32 (dup pairs): a = numerator * 1/z
            int c = t & 31, r0 = t >> 5;   // r0 0..3
            float rz = __fdividef(1.0f, zb[jbase + c]);
            #pragma unroll
            for (int p = 0; p < 16; p++) {
                int r = r0 + 4 * p;
                float v = scb[(size_t)(i0 + r) * NN + jbase + c] * rz;
                sA2[r * 33 + c] = make_float2(v, v);
            }
        }
        {   // h tile 32x128
            #pragma unroll
            for (int r = 0; r < 32; r++)
                sH[r * 130 + t] = Hb[(size_t)(jbase + r) * DD + t];
        }
        __syncthreads();
        for (int kk = 0; kk < 32; kk++) {
            uint64_t bp[4];
            #pragma unroll
            for (int jj = 0; jj < 4; jj++)
                bp[jj] = *(const uint64_t*)&sH[kk * 130 + jj * 32 + tx * 2];
            #pragma unroll
            for (int i = 0; i < 8; i++) {
                uint64_t ap = *(const uint64_t*)&sA2[(ty * 8 + i) * 33 + kk];
                #pragma unroll
                for (int jj = 0; jj < 4; jj++)
                    ffma2(accp[i][jj], ap, bp[jj]);
            }
        }
        __syncthreads();
    }
    float* hpb = g_hp + (size_t)b * NN * DD;
    #pragma unroll
    for (int i = 0; i < 8; i++) {
        int row = i0 + ty * 8 + i;
        #pragma unroll
        for (int jj = 0; jj < 4; jj++) {
            float2 v = unpack2(accp[i][jj]);
            v.x = fmaxf(v.x, 0.f); v.y = fmaxf(v.y, 0.f);
            *(float2*)&hpb[(size_t)row * DD + jj * 32 + tx * 2] = v;
        }
    }
}

// ---------------- K6: gates + output ----------------
__global__ __launch_bounds__(256) void k_out(const float* __restrict__ x,
        const float* __restrict__ wi_u, const float* __restrict__ wi_x,
        const float* __restrict__ wf_u, const float* __restrict__ wf_x,
        const float* __restrict__ wo_u, const float* __restrict__ wo_x,
        float* __restrict__ out) {
    int node = blockIdx.x * 8 + (threadIdx.x >> 5);
    int lane = threadIdx.x & 31;
    size_t base = (size_t)node * DD;
    float hp4[4], x4[4];
    float si = 0.f, sf = 0.f, so = 0.f;
    #pragma unroll
    for (int i = 0; i < 4; i++) {
        int d = lane + 32 * i;
        hp4[i] = g_hp[base + d];
        x4[i]  = x[base + d];
        si += hp4[i] * wi_u[d] + x4[i] * wi_x[d];
        sf += hp4[i] * wf_u[d] + x4[i] * wf_x[d];
        so += hp4[i] * wo_u[d] + x4[i] * wo_x[d];
    }
    #pragma unroll
    for (int off = 16; off; off >>= 1) {
        si += __shfl_xor_sync(0xffffffffu, si, off);
        sf += __shfl_xor_sync(0xffffffffu, sf, off);
        so += __shfl_xor_sync(0xffffffffu, so, off);
    }
    float ic = 1.f / (1.f + __expf(-si));
    float fc = 1.f / (1.f + __expf(-sf));
    float oc = 1.f / (1.f + __expf(-so));
    #pragma unroll
    for (int i = 0; i < 4; i++) {
        int d = lane + 32 * i;
        out[base + d] = oc * tanhf(ic * hp4[i] + fc * x4[i]);
    }
}

// ---------------- launch ----------------
extern "C" void kernel_launch(void* const* d_in, const int* in_sizes, int n_in,
                              void* d_out, int out_size) {
    const float* x    = (const float*)d_in[0];
    const float* adj  = (const float*)d_in[1];
    const float* Ww   = (const float*)d_in[2];
    const float* Wb   = (const float*)d_in[3];
    const float* A    = (const float*)d_in[4];
    const float* wi_u = (const float*)d_in[5];
    const float* wi_x = (const float*)d_in[6];
    const float* wf_u = (const float*)d_in[7];
    const float* wf_x = (const float*)d_in[8];
    const float* wo_u = (const float*)d_in[9];
    const float* wo_x = (const float*)d_in[10];
    float* out = (float*)d_out;

    cudaFuncSetAttribute(k_scores, cudaFuncAttributeMaxDynamicSharedMemorySize, SMEM_K3);

    k_prep<<<64, 256>>>(Ww, A);
    k_h_g<<<BN / 64, 256>>>(x, Wb);
    k_scores<<<dim3(36, BB), 256, SMEM_K3>>>(adj);
    k_hprime<<<dim3(NN / 64, BB), 128>>>();
    k_out<<<BN / 8, 256>>>(x, wi_u, wi_x, wf_u, wf_x, wo_u, wo_x, out);
}